// round 5
// baseline (speedup 1.0000x reference)
#include <cuda_runtime.h>
#include <stdint.h>

// Problem constants
#define B     1024
#define S     2048
#define R1    20000
#define R2    40000

#define MAIN_THREADS 512
#define RPP   5000                 // rates per partition (exact: rid is 0..R-1)
#define P1    (R1 / RPP)           // 4 partitions, phase A
#define P2    (R2 / RPP)           // 8 partitions, phase B
#define EPTP  10                   // entries per thread per partition (5000/512 -> pad 5120)
#define PART_PAD (EPTP * MAIN_THREADS)   // 5120
#define KPAD  2048u                // dummy key -> scratch accumulator slot

// ---------------- static device scratch (no runtime allocation) ----------------
__device__ int       g_counts1[P1 * S];
__device__ int       g_counts2[P2 * S];
__device__ int       g_cur1[P1 * S];
__device__ int       g_cur2[P2 * S];
// Per-partition transposed, key-grouped entry streams.
//   e1 = ra | k<<11 | rid_rel<<23            (11 + 12 + 13 bits)
//   e2 = ra | rb<<11 | k<<22 | rid_rel<<34   (11 + 11 + 12 + 13 bits)
__device__ uint64_t  g_e1t[P1 * PART_PAD];
__device__ uint64_t  g_e2t[P2 * PART_PAD];

__device__ __forceinline__ int transposeP(int pos) {
    return (pos % EPTP) * MAIN_THREADS + pos / EPTP;
}

// ---------------- prep kernels ----------------

__global__ void init_counts_kernel() {
    int i = blockIdx.x * blockDim.x + threadIdx.x;
    if (i < P1 * S) g_counts1[i] = 0;
    if (i < P2 * S) g_counts2[i] = 0;
}

__global__ void hist_kernel(const int* __restrict__ inds_1p,
                            const int* __restrict__ inds_2p) {
    int i = blockIdx.x * blockDim.x + threadIdx.x;
    if (i < R1) {
        int part = i / RPP;
        atomicAdd(&g_counts1[part * S + inds_1p[i]], 1);
    } else if (i < R1 + R2) {
        int j = i - R1;
        int part = j / RPP;
        atomicAdd(&g_counts2[part * S + inds_2p[j]], 1);
    }
}

// One CTA per partition: exclusive scan over its 2048 bins.
__global__ void scan_kernel() {
    __shared__ int buf[2][S];
    const int tid  = threadIdx.x;       // 1024 threads, 2 elems each
    const int part = blockIdx.x;        // 0..P1+P2-1

    const int* cnt = (part < P1) ? (g_counts1 + part * S)
                                 : (g_counts2 + (part - P1) * S);
    int*       cur = (part < P1) ? (g_cur1 + part * S)
                                 : (g_cur2 + (part - P1) * S);

    buf[0][tid]        = cnt[tid];
    buf[0][tid + 1024] = cnt[tid + 1024];
    __syncthreads();

    int src = 0;
    for (int off = 1; off < S; off <<= 1) {
        int i0 = tid, i1 = tid + 1024;
        int v0 = buf[src][i0] + (i0 >= off ? buf[src][i0 - off] : 0);
        int v1 = buf[src][i1] + (i1 >= off ? buf[src][i1 - off] : 0);
        __syncthreads();
        buf[1 - src][i0] = v0;
        buf[1 - src][i1] = v1;
        __syncthreads();
        src ^= 1;
    }
    cur[tid]        = (tid == 0) ? 0 : buf[src][tid - 1];
    cur[tid + 1024] = buf[src][tid + 1023];
}

__global__ void scatter_kernel(const int* __restrict__ inds_1r,
                               const int* __restrict__ inds_1p,
                               const int* __restrict__ inds_2r,
                               const int* __restrict__ inds_2p) {
    int i = blockIdx.x * blockDim.x + threadIdx.x;
    if (i < R1) {
        int part = i / RPP;
        int rrel = i - part * RPP;
        int p    = inds_1p[i];
        int pos  = atomicAdd(&g_cur1[part * S + p], 1);
        g_e1t[part * PART_PAD + transposeP(pos)] =
              (uint64_t)(uint32_t)inds_1r[i]
            | ((uint64_t)(uint32_t)p    << 11)
            | ((uint64_t)(uint32_t)rrel << 23);
    } else if (i < R1 + R2) {
        int j    = i - R1;
        int part = j / RPP;
        int rrel = j - part * RPP;
        int p    = inds_2p[j];
        int pos  = atomicAdd(&g_cur2[part * S + p], 1);
        g_e2t[part * PART_PAD + transposeP(pos)] =
              (uint64_t)(uint32_t)inds_2r[2 * j]
            | ((uint64_t)(uint32_t)inds_2r[2 * j + 1] << 11)
            | ((uint64_t)(uint32_t)p                  << 22)
            | ((uint64_t)(uint32_t)rrel               << 34);
    }
}

// Fill padding slots (positions RPP..PART_PAD-1 of every partition).
__global__ void pad_kernel() {
    int i = blockIdx.x * blockDim.x + threadIdx.x;
    int npad = PART_PAD - RPP;                 // 120
    if (i < P1 * npad) {
        int part = i / npad, q = i % npad;
        g_e1t[part * PART_PAD + transposeP(RPP + q)] = ((uint64_t)KPAD << 11);
    } else if (i < (P1 + P2) * npad) {
        int t = i - P1 * npad;
        int part = t / npad, q = t % npad;
        g_e2t[part * PART_PAD + transposeP(RPP + q)] = ((uint64_t)KPAD << 22);
    }
}

// ---------------- main kernel ----------------
// One CTA per batch row; 12 rate partitions staged sequentially in a 20KB
// SMEM buffer. Each thread sweeps 10 entries/partition (loaded branch-free
// into registers, MLP=10), accumulating per-key in a register and flushing
// to the SMEM accumulator on key change.
//
// SMEM: y(2048) + acc(2052, slot 2048 = pad sink) + rbuf(5000) = 36,400 B
// -> 3-4 CTAs/SM instead of 1.

#define ACC_FLOATS 2052
#define SMEM_FLOATS (S + ACC_FLOATS + RPP)   // 9100 floats

__global__ __launch_bounds__(MAIN_THREADS, 3)
void reaction_main_kernel(const float* __restrict__ y_in,
                          const float* __restrict__ rates_1st,
                          const float* __restrict__ rates_2nd,
                          float* __restrict__ y_out) {
    extern __shared__ float sm[];
    float* y_s   = sm;                   // [S]
    float* acc_s = sm + S;               // [ACC_FLOATS]
    float* rbuf  = sm + S + ACC_FLOATS;  // [RPP]

    const int b   = blockIdx.x;
    const int tid = threadIdx.x;

    // Load y row (one float4/thread) and zero the accumulator.
    {
        const float4* src = (const float4*)(y_in + (size_t)b * S);
        ((float4*)y_s)[tid] = src[tid];
        #pragma unroll
        for (int i = tid; i < ACC_FLOATS; i += MAIN_THREADS)
            acc_s[i] = 0.f;
    }

    // ---- Phase A: 4 partitions ----
    #pragma unroll 1
    for (int part = 0; part < P1; ++part) {
        __syncthreads();   // previous partition's rbuf reads done
        {
            const float4* src = (const float4*)(rates_1st + (size_t)b * R1 + part * RPP);
            #pragma unroll
            for (int i = tid; i < RPP / 4; i += MAIN_THREADS)
                ((float4*)rbuf)[i] = __ldcs(src + i);
        }
        __syncthreads();

        const uint64_t* __restrict__ ep = g_e1t + part * PART_PAD + tid;
        uint64_t ebuf[EPTP];
        #pragma unroll
        for (int u = 0; u < EPTP; ++u)
            ebuf[u] = ep[u * MAIN_THREADS];      // 10 independent coalesced LDG.64

        unsigned curk = KPAD;
        float    a    = 0.f;
        #pragma unroll
        for (int u = 0; u < EPTP; ++u) {
            uint64_t e   = ebuf[u];
            unsigned ra  = (unsigned)e & 2047u;
            unsigned k   = ((unsigned)(e >> 11)) & 4095u;
            unsigned rid = (unsigned)(e >> 23);
            float v = y_s[ra] * rbuf[rid];
            if (k != curk) {
                atomicAdd(&acc_s[curk], a);
                curk = k; a = v;
            } else {
                a += v;
            }
        }
        atomicAdd(&acc_s[curk], a);
    }

    // ---- Phase B: 8 partitions ----
    #pragma unroll 1
    for (int part = 0; part < P2; ++part) {
        __syncthreads();
        {
            const float4* src = (const float4*)(rates_2nd + (size_t)b * R2 + part * RPP);
            #pragma unroll
            for (int i = tid; i < RPP / 4; i += MAIN_THREADS)
                ((float4*)rbuf)[i] = __ldcs(src + i);
        }
        __syncthreads();

        const uint64_t* __restrict__ ep = g_e2t + part * PART_PAD + tid;
        uint64_t ebuf[EPTP];
        #pragma unroll
        for (int u = 0; u < EPTP; ++u)
            ebuf[u] = ep[u * MAIN_THREADS];

        unsigned curk = KPAD;
        float    a    = 0.f;
        #pragma unroll
        for (int u = 0; u < EPTP; ++u) {
            uint64_t e   = ebuf[u];
            unsigned ra  = (unsigned)e & 2047u;
            unsigned rb  = ((unsigned)(e >> 11)) & 2047u;
            unsigned k   = ((unsigned)(e >> 22)) & 4095u;
            unsigned rid = (unsigned)(e >> 34);
            float v = y_s[ra] * y_s[rb] * rbuf[rid];
            if (k != curk) {
                atomicAdd(&acc_s[curk], a);
                curk = k; a = v;
            } else {
                a += v;
            }
        }
        atomicAdd(&acc_s[curk], a);
    }
    __syncthreads();

    // ---- write out (coalesced float4, first S slots only) ----
    ((float4*)(y_out + (size_t)b * S))[tid] = ((const float4*)acc_s)[tid];
}

// ---------------- launch ----------------

extern "C" void kernel_launch(void* const* d_in, const int* in_sizes, int n_in,
                              void* d_out, int out_size) {
    const float* y_in      = (const float*)d_in[0];
    const float* rates_1st = (const float*)d_in[1];
    const float* rates_2nd = (const float*)d_in[2];
    const int*   inds_1r   = (const int*)d_in[3];
    const int*   inds_1p   = (const int*)d_in[4];
    const int*   inds_2r   = (const int*)d_in[5];
    const int*   inds_2p   = (const int*)d_in[6];
    float*       y_out     = (float*)d_out;

    cudaFuncSetAttribute(reaction_main_kernel,
                         cudaFuncAttributeMaxDynamicSharedMemorySize,
                         SMEM_FLOATS * (int)sizeof(float));

    // Entry-stream build (rebuilt every launch; deterministic)
    init_counts_kernel<<<(P2 * S + 255) / 256, 256>>>();
    hist_kernel<<<(R1 + R2 + 255) / 256, 256>>>(inds_1p, inds_2p);
    scan_kernel<<<P1 + P2, 1024>>>();
    scatter_kernel<<<(R1 + R2 + 255) / 256, 256>>>(inds_1r, inds_1p, inds_2r, inds_2p);
    pad_kernel<<<((P1 + P2) * (PART_PAD - RPP) + 255) / 256, 256>>>();

    // Main pass: one CTA per batch row
    reaction_main_kernel<<<B, MAIN_THREADS, SMEM_FLOATS * sizeof(float)>>>(
        y_in, rates_1st, rates_2nd, y_out);
}

// round 6
// speedup vs baseline: 1.7202x; 1.7202x over previous
#include <cuda_runtime.h>
#include <stdint.h>

// Problem constants
#define B     1024
#define S     2048
#define R1    20000
#define R2    40000

#define MAIN_THREADS 512
#define NPART 3                    // part0 = rates_1st; part1,2 = rates_2nd halves
#define RPP   20000                // rates (and real entries) per partition
#define EPT   40                   // entries per thread per partition (pad 20480)
#define PART_PAD (EPT * MAIN_THREADS)   // 20480
#define KPAD  2048u                // pad-entry key (harmless acc slot)
#define SINK  2049                 // redirect target for non-closing stores
#define ACC_FLOATS 2056
#define CHUNK 8

// ---------------- static device scratch (no runtime allocation) ----------------
__device__ int       g_counts[NPART][S];
__device__ int       g_cur[NPART][S];
// Key-grouped, transposed entry streams (EPT uniform across partitions).
//   part0:  e = ra | k<<11 | rid<<23            (11 + 12 + 15 bits)
//   part1+: e = ra | rb<<11 | k<<22 | rid<<34   (11 + 11 + 12 + 15 bits)
__device__ uint64_t  g_et[NPART][PART_PAD];

__device__ __forceinline__ int transposeP(int pos) {
    return (pos % EPT) * MAIN_THREADS + pos / EPT;
}

// ---------------- prep kernels ----------------

__global__ void init_counts_kernel() {
    int i = blockIdx.x * blockDim.x + threadIdx.x;
    if (i < NPART * S) (&g_counts[0][0])[i] = 0;
}

__global__ void hist_kernel(const int* __restrict__ inds_1p,
                            const int* __restrict__ inds_2p) {
    int i = blockIdx.x * blockDim.x + threadIdx.x;
    if (i < R1) {
        atomicAdd(&g_counts[0][inds_1p[i]], 1);
    } else if (i < R1 + R2) {
        int j = i - R1;
        int part = 1 + (j >= RPP);
        atomicAdd(&g_counts[part][inds_2p[j]], 1);
    }
}

// One CTA per partition: exclusive scan over its 2048 bins -> running cursors.
__global__ void scan_kernel() {
    __shared__ int buf[2][S];
    const int tid  = threadIdx.x;       // 1024 threads, 2 elems each
    const int part = blockIdx.x;        // 0..NPART-1

    const int* cnt = g_counts[part];
    int*       cur = g_cur[part];

    buf[0][tid]        = cnt[tid];
    buf[0][tid + 1024] = cnt[tid + 1024];
    __syncthreads();

    int src = 0;
    for (int off = 1; off < S; off <<= 1) {
        int i0 = tid, i1 = tid + 1024;
        int v0 = buf[src][i0] + (i0 >= off ? buf[src][i0 - off] : 0);
        int v1 = buf[src][i1] + (i1 >= off ? buf[src][i1 - off] : 0);
        __syncthreads();
        buf[1 - src][i0] = v0;
        buf[1 - src][i1] = v1;
        __syncthreads();
        src ^= 1;
    }
    cur[tid]        = (tid == 0) ? 0 : buf[src][tid - 1];
    cur[tid + 1024] = buf[src][tid + 1023];
}

// Scatter entries into key-grouped transposed slots + write pad entries.
__global__ void scatter_pad_kernel(const int* __restrict__ inds_1r,
                                   const int* __restrict__ inds_1p,
                                   const int* __restrict__ inds_2r,
                                   const int* __restrict__ inds_2p) {
    int i = blockIdx.x * blockDim.x + threadIdx.x;
    if (i < R1) {
        int p   = inds_1p[i];
        int pos = atomicAdd(&g_cur[0][p], 1);
        g_et[0][transposeP(pos)] =
              (uint64_t)(uint32_t)inds_1r[i]
            | ((uint64_t)(uint32_t)p << 11)
            | ((uint64_t)(uint32_t)i << 23);
    } else if (i < R1 + R2) {
        int j    = i - R1;
        int part = 1 + (j >= RPP);
        int rrel = j - (part - 1) * RPP;
        int p    = inds_2p[j];
        int pos  = atomicAdd(&g_cur[part][p], 1);
        g_et[part][transposeP(pos)] =
              (uint64_t)(uint32_t)inds_2r[2 * j]
            | ((uint64_t)(uint32_t)inds_2r[2 * j + 1] << 11)
            | ((uint64_t)(uint32_t)p                  << 22)
            | ((uint64_t)(uint32_t)rrel               << 34);
    } else if (i < R1 + R2 + NPART * (PART_PAD - RPP)) {
        int q    = i - (R1 + R2);
        int part = q / (PART_PAD - RPP);
        int slot = RPP + q % (PART_PAD - RPP);
        uint64_t e = (part == 0) ? ((uint64_t)KPAD << 11) : ((uint64_t)KPAD << 22);
        g_et[part][transposeP(slot)] = e;
    }
}

// ---------------- main kernel ----------------
// One CTA per batch row; 3 uniform partitions of 20000 rates staged in an
// 80KB SMEM buffer (occ = 2 CTAs/SM). Each thread owns a contiguous slice of
// the key-sorted entry stream (coalesced via transposed layout, chunked
// MLP=8 loads). Inner loop is 100% branch-free: run-close is an unconditional
// SMEM read-modify-write through a SEL-redirected address (interior keys are
// thread-exclusive); each slice's first/last (possibly shared) runs are
// resolved with <=2 SMEM atomics per thread per partition, after a barrier.

#define SMEM_FLOATS (S + ACC_FLOATS + RPP)   // 24104 floats = 96,416 B

template <bool SECOND>
__device__ __forceinline__ void sweep_partition(
    const uint64_t* __restrict__ ep,   // g_et[part] + tid
    const float* __restrict__ y_s,
    const float* __restrict__ rbuf,
    float* __restrict__ acc_s,
    unsigned& firstk, float& firstv, unsigned& fdone,
    unsigned& lastk, float& lastv)
{
    uint64_t buf0[CHUNK], buf1[CHUNK];
    #pragma unroll
    for (int u = 0; u < CHUNK; ++u)
        buf0[u] = ep[u * MAIN_THREADS];

    unsigned curk = 0; float a = 0.f;
    unsigned first_done = 0;
    firstk = SINK; firstv = 0.f;

    #pragma unroll
    for (int c = 0; c < EPT / CHUNK; ++c) {
        uint64_t* cur = (c & 1) ? buf1 : buf0;
        uint64_t* nxt = (c & 1) ? buf0 : buf1;
        if (c + 1 < EPT / CHUNK) {
            const uint64_t* np = ep + (c + 1) * CHUNK * MAIN_THREADS;
            #pragma unroll
            for (int u = 0; u < CHUNK; ++u)
                nxt[u] = np[u * MAIN_THREADS];
        }
        #pragma unroll
        for (int u = 0; u < CHUNK; ++u) {
            uint64_t e = cur[u];
            unsigned ra, k, rid;
            float v;
            if (SECOND) {
                ra  = (unsigned)e & 2047u;
                unsigned rb = ((unsigned)(e >> 11)) & 2047u;
                k   = ((unsigned)(e >> 22)) & 4095u;
                rid = (unsigned)(e >> 34);
                v = y_s[ra] * y_s[rb] * rbuf[rid];
            } else {
                ra  = (unsigned)e & 2047u;
                k   = ((unsigned)(e >> 11)) & 4095u;
                rid = (unsigned)(e >> 23);
                v = y_s[ra] * rbuf[rid];
            }
            if (c == 0 && u == 0) {
                // peel: prime the first run
                curk = k; a = v;
            } else {
                unsigned same = (k == curk) ? 1u : 0u;
                float    closed  = a;
                unsigned closedk = curk;
                // close previous run: plain RMW, redirected to SINK unless
                // this is a real close of a non-first (interior) run.
                unsigned do_store = (1u - same) & first_done;
                float* addr = do_store ? (acc_s + closedk) : (acc_s + SINK);
                *addr += closed;                        // unconditional LDS+FADD+STS
                // capture first-run partial (shared with prev thread)
                unsigned cap = (1u - same) & (1u - first_done);
                firstk = cap ? closedk : firstk;
                firstv = cap ? closed  : firstv;
                first_done |= (1u - same);
                a    = same ? (a + v) : v;
                curk = k;
            }
        }
    }
    fdone = first_done;
    lastk = curk; lastv = a;
}

__global__ __launch_bounds__(MAIN_THREADS, 2)
void reaction_main_kernel(const float* __restrict__ y_in,
                          const float* __restrict__ rates_1st,
                          const float* __restrict__ rates_2nd,
                          float* __restrict__ y_out) {
    extern __shared__ float sm[];
    float* y_s   = sm;                   // [S]
    float* acc_s = sm + S;               // [ACC_FLOATS]
    float* rbuf  = sm + S + ACC_FLOATS;  // [RPP]

    const int b   = blockIdx.x;
    const int tid = threadIdx.x;

    // Load y row (one float4/thread) and zero the accumulator.
    {
        const float4* src = (const float4*)(y_in + (size_t)b * S);
        ((float4*)y_s)[tid] = src[tid];
        #pragma unroll
        for (int i = tid; i < ACC_FLOATS; i += MAIN_THREADS)
            acc_s[i] = 0.f;
    }

    const float* rate_base[NPART] = {
        rates_1st + (size_t)b * R1,
        rates_2nd + (size_t)b * R2,
        rates_2nd + (size_t)b * R2 + RPP
    };

    #pragma unroll 1
    for (int part = 0; part < NPART; ++part) {
        __syncthreads();   // prior sweep's rbuf reads + acc stores done
        {
            const float4* src = (const float4*)rate_base[part];
            #pragma unroll
            for (int i = tid; i < RPP / 4; i += MAIN_THREADS)
                ((float4*)rbuf)[i] = __ldcs(src + i);
        }
        __syncthreads();

        unsigned firstk, fdone, lastk;
        float firstv, lastv;
        if (part == 0)
            sweep_partition<false>(g_et[0] + tid, y_s, rbuf, acc_s,
                                   firstk, firstv, fdone, lastk, lastv);
        else if (part == 1)
            sweep_partition<true>(g_et[1] + tid, y_s, rbuf, acc_s,
                                  firstk, firstv, fdone, lastk, lastv);
        else
            sweep_partition<true>(g_et[2] + tid, y_s, rbuf, acc_s,
                                  firstk, firstv, fdone, lastk, lastv);

        __syncthreads();   // interior plain stores visible before boundary atomics
        // boundary runs (possibly shared with neighbor threads): atomics
        atomicAdd(&acc_s[lastk], lastv);
        if (fdone) atomicAdd(&acc_s[firstk], firstv);
    }
    __syncthreads();

    // ---- write out (coalesced float4, first S slots only) ----
    ((float4*)(y_out + (size_t)b * S))[tid] = ((const float4*)acc_s)[tid];
}

// ---------------- launch ----------------

extern "C" void kernel_launch(void* const* d_in, const int* in_sizes, int n_in,
                              void* d_out, int out_size) {
    const float* y_in      = (const float*)d_in[0];
    const float* rates_1st = (const float*)d_in[1];
    const float* rates_2nd = (const float*)d_in[2];
    const int*   inds_1r   = (const int*)d_in[3];
    const int*   inds_1p   = (const int*)d_in[4];
    const int*   inds_2r   = (const int*)d_in[5];
    const int*   inds_2p   = (const int*)d_in[6];
    float*       y_out     = (float*)d_out;

    cudaFuncSetAttribute(reaction_main_kernel,
                         cudaFuncAttributeMaxDynamicSharedMemorySize,
                         SMEM_FLOATS * (int)sizeof(float));

    // Entry-stream build (rebuilt every launch; deterministic)
    init_counts_kernel<<<(NPART * S + 255) / 256, 256>>>();
    hist_kernel<<<(R1 + R2 + 255) / 256, 256>>>(inds_1p, inds_2p);
    scan_kernel<<<NPART, 1024>>>();
    int scat_n = R1 + R2 + NPART * (PART_PAD - RPP);
    scatter_pad_kernel<<<(scat_n + 255) / 256, 256>>>(inds_1r, inds_1p, inds_2r, inds_2p);

    // Main pass: one CTA per batch row
    reaction_main_kernel<<<B, MAIN_THREADS, SMEM_FLOATS * sizeof(float)>>>(
        y_in, rates_1st, rates_2nd, y_out);
}